// round 1
// baseline (speedup 1.0000x reference)
#include <cuda_runtime.h>
#include <math.h>

// Block floating-point quantization:
//   per 16-element block: e = floor(log2(max|x|)), scale = 2^(e-7)
//   q = clamp(rint(x/scale), -128, 127) * scale ; zero block -> 0
//
// Layout: one float4 (4 elems) per thread, 4 consecutive lanes share one
// 16-element block. Warp loads are 512B contiguous (perfect coalescing).
// Block max via 2x shfl_xor. Exponent via bit extraction (no log2f).

__global__ __launch_bounds__(256) void bfp_quant_kernel(
    const float4* __restrict__ in, float4* __restrict__ out, int n4)
{
    int i = blockIdx.x * blockDim.x + threadIdx.x;
    if (i >= n4) return;

    float4 v = in[i];

    float a = fmaxf(fmaxf(fabsf(v.x), fabsf(v.y)),
                    fmaxf(fabsf(v.z), fabsf(v.w)));
    // reduce max over the 4-lane group (one 16-elem block)
    a = fmaxf(a, __shfl_xor_sync(0xffffffffu, a, 1));
    a = fmaxf(a, __shfl_xor_sync(0xffffffffu, a, 2));

    // e = floor(log2(a)) for a > 0 ; a == 0 -> safe_max = 1 -> e = 0
    int abits = __float_as_int(a);
    int e;
    if (a > 0.0f) {
        if ((abits & 0x7F800000) != 0) {
            e = ((abits >> 23) & 0xFF) - 127;      // normal float
        } else {
            e = ilogbf(a);                          // denormal max (rare)
        }
    } else {
        e = 0;                                      // zero block
    }

    int eb = e - 7;   // mantissa_bits - 1 = 7
    float scale, inv_scale;
    if (eb >= -126 && eb <= 126) {
        scale     = __int_as_float((eb + 127) << 23);
        inv_scale = __int_as_float((127 - eb) << 23);
    } else {
        scale     = ldexpf(1.0f, eb);
        inv_scale = ldexpf(1.0f, -eb);
    }

    float4 r;
    r.x = fminf(fmaxf(rintf(v.x * inv_scale), -128.0f), 127.0f) * scale;
    r.y = fminf(fmaxf(rintf(v.y * inv_scale), -128.0f), 127.0f) * scale;
    r.z = fminf(fmaxf(rintf(v.z * inv_scale), -128.0f), 127.0f) * scale;
    r.w = fminf(fmaxf(rintf(v.w * inv_scale), -128.0f), 127.0f) * scale;

    out[i] = r;
}

extern "C" void kernel_launch(void* const* d_in, const int* in_sizes, int n_in,
                              void* d_out, int out_size)
{
    const float4* x = (const float4*)d_in[0];
    float4* out = (float4*)d_out;
    int n = in_sizes[0];          // 4*4096*4096 = 67108864, divisible by 4
    int n4 = n / 4;
    int threads = 256;
    int blocks = (n4 + threads - 1) / threads;
    bfp_quant_kernel<<<blocks, threads>>>(x, out, n4);
}